// round 9
// baseline (speedup 1.0000x reference)
#include <cuda_runtime.h>

#define T_HOR 100
#define B_BATCH 512
#define REGU 1e-6f

typedef unsigned long long ull;

__device__ float g_K[B_BATCH * T_HOR * 8 * 24];
__device__ float g_kv[B_BATCH * T_HOR * 8];

__device__ __forceinline__ ull pack2(float s) {
    ull d; asm("mov.b64 %0, {%1, %1};" : "=l"(d) : "f"(s)); return d;
}
__device__ __forceinline__ void ffma2(ull& d, ull a, ull b) {
    asm("fma.rn.f32x2 %0, %1, %2, %0;" : "+l"(d) : "l"(a), "l"(b));
}
__device__ __forceinline__ float2 unpack2(ull v) {
    float2 r; asm("mov.b64 {%0, %1}, %2;" : "=f"(r.x), "=f"(r.y) : "l"(v)); return r;
}
__device__ __forceinline__ void cp16(unsigned sa, const void* g) {
    asm volatile("cp.async.cg.shared.global [%0], [%1], 16;" :: "r"(sa), "l"(g));
}
__device__ __forceinline__ void cp4(unsigned sa, const void* g) {
    asm volatile("cp.async.ca.shared.global [%0], [%1], 4;" :: "r"(sa), "l"(g));
}

extern "C" __global__ void __launch_bounds__(128, 4)
lqr_kernel(const float* __restrict__ d_x0,
           const float* __restrict__ d_C,
           const float* __restrict__ d_c,
           const float* __restrict__ d_Cf,
           const float* __restrict__ d_cf,
           const float* __restrict__ d_xref,
           const float* __restrict__ d_uref,
           const float* __restrict__ d_A,
           const float* __restrict__ d_B,
           float* __restrict__ d_out)
{
    __shared__ __align__(16) float sAB[24 * 36];
    __shared__ __align__(16) float sV[24 * 28];
    __shared__ __align__(16) float sC[2][32 * 36];
    __shared__ __align__(16) float sSc[2][64];     // [0..31]=c, [32..55]=xref, [56..63]=uref
    __shared__ __align__(16) float sG[24 * 36];
    __shared__ __align__(16) float sH[32 * 36];
    __shared__ __align__(16) float sK[8 * 28];
    __shared__ __align__(16) float sQi[8 * 9];
    __shared__ __align__(16) float sQ[32], sv[32];
    __shared__ float skv[8], su[8];
    __shared__ float sx[2][24];

    const int tid = threadIdx.x;
    const int b = blockIdx.x;

    // stage E map: tid>>1 over 21 lower tiles (6x6)
    int e_ti = 0, e_tk = 0;
    {
        const int tt = tid >> 1;
        int s = 0;
        #pragma unroll
        for (int i = 0; i < 6; i++) {
            if (tt >= s && tt < s + i + 1) { e_ti = i; e_tk = tt - s; }
            s += i + 1;
        }
    }
    // stage B' map (warps 1-3): 33 tiles (Qxx 21 + Qux 12), 2 thr/tile
    int q_r0 = 0, q_k0 = 0;
    {
        const int w = tid - 32;                 // 0..95, valid < 66
        const int tt = w >> 1;
        if (w >= 0 && w < 66) {
            int bi = 0, bk = 0;
            if (tt < 21) {
                int s = 0;
                #pragma unroll
                for (int i = 0; i < 6; i++) {
                    if (tt >= s && tt < s + i + 1) { bi = i; bk = tt - s; }
                    s += i + 1;
                }
            } else {
                bi = 6 + (tt - 21) / 6;
                bk = (tt - 21) % 6;
            }
            q_r0 = bi * 4 + (w & 1) * 2;
            q_k0 = bk * 4;
        }
    }
    // warp0 Quu row map (threads 0..11)
    int u_row = 24, u_k0 = 24;
    if (tid < 4)       { u_row = 24 + tid;       u_k0 = 24; }
    else if (tid < 8)  { u_row = 28 + (tid - 4); u_k0 = 24; }
    else if (tid < 12) { u_row = 28 + (tid - 8); u_k0 = 28; }

    // ---------------- preamble ----------------
    for (int e = tid; e < 24 * 32; e += 128) {
        int j = e >> 5, cc = e & 31;
        sAB[j * 36 + cc] = (cc < 24) ? d_A[j * 24 + cc] : d_B[j * 8 + (cc - 24)];
    }
    for (int e = tid; e < 576; e += 128) {
        int i = e / 24, j = e - i * 24;
        sV[i * 28 + j] = d_Cf[(size_t)b * 1024 + i * 32 + j];
    }
    if (tid < 24) sQ[tid] = d_xref[((size_t)b * 101 + 100) * 24 + tid];
    {
        const float4* C4 = (const float4*)(d_C + ((size_t)b * T_HOR + 99) * 1024);
        #pragma unroll
        for (int ss = 0; ss < 2; ss++) {
            const int s = tid + ss * 128;
            *(float4*)(sC[0] + (s >> 3) * 36 + ((s & 7) << 2)) = C4[s];
        }
        if (tid < 32)
            sSc[0][tid] = d_c[((size_t)b * T_HOR + 99) * 32 + tid];
        else if (tid < 56)
            sSc[0][tid] = d_xref[((size_t)b * 101 + 99) * 24 + (tid - 32)];
        else if (tid < 64)
            sSc[0][tid] = d_uref[((size_t)b * T_HOR + 99) * 8 + (tid - 56)];
    }
    __syncthreads();
    if (tid < 24) {
        float acc = d_cf[b * 32 + tid];
        #pragma unroll
        for (int j = 0; j < 24; j++) acc -= sV[tid * 28 + j] * sQ[j];
        sv[tid] = acc;
    }
    __syncthreads();

    // ---------------- backward Riccati ----------------
    int buf = 0;
    for (int t = 99; t >= 0; --t) {
        const float* sCb  = sC[buf];
        const float* sScb = sSc[buf];

        if (t > 0) {
            const float4* src = (const float4*)(d_C + ((size_t)b * T_HOR + t - 1) * 1024);
            float* dst = sC[buf ^ 1];
            #pragma unroll
            for (int ss = 0; ss < 2; ss++) {
                const int s = tid + ss * 128;
                cp16((unsigned)__cvta_generic_to_shared(dst + (s >> 3) * 36 + ((s & 7) << 2)),
                     src + s);
            }
            if (tid < 64) {
                const float* g;
                if (tid < 32)      g = d_c    + ((size_t)b * T_HOR + t - 1) * 32 + tid;
                else if (tid < 56) g = d_xref + ((size_t)b * 101 + t - 1) * 24 + (tid - 32);
                else               g = d_uref + ((size_t)b * T_HOR + t - 1) * 8 + (tid - 56);
                cp4((unsigned)__cvta_generic_to_shared(&sSc[buf ^ 1][tid]), g);
            }
            asm volatile("cp.async.commit_group;");
        }

        // ---- stage A: G = V*[A|B] (96 thr, 2x4, f32x2) ; Q = [Qx|Qu] (32 thr)
        if (tid < 96) {
            const int i0 = (tid >> 3) * 2, c4 = (tid & 7) << 2;
            ull aL0 = 0, aH0 = 0, aL1 = 0, aH1 = 0;
            #pragma unroll
            for (int j = 0; j < 24; j++) {
                const float2 vv = *(const float2*)(sV + j * 28 + i0);
                const ulonglong2 ab = *(const ulonglong2*)(sAB + j * 36 + c4);
                const ull v0 = pack2(vv.x), v1 = pack2(vv.y);
                ffma2(aL0, v0, ab.x); ffma2(aH0, v0, ab.y);
                ffma2(aL1, v1, ab.x); ffma2(aH1, v1, ab.y);
            }
            *(ulonglong2*)(sG + i0 * 36 + c4)       = make_ulonglong2(aL0, aH0);
            *(ulonglong2*)(sG + (i0 + 1) * 36 + c4) = make_ulonglong2(aL1, aH1);
        } else {
            const int r = tid - 96;
            float acc = sScb[r];
            #pragma unroll
            for (int j4 = 0; j4 < 8; j4++) {
                const float4 cr = *(const float4*)(sCb + r * 36 + j4 * 4);
                const float4 zz = *(const float4*)(sScb + 32 + j4 * 4);
                acc -= cr.x * zz.x + cr.y * zz.y + cr.z * zz.z + cr.w * zz.w;
            }
            #pragma unroll
            for (int j = 0; j < 24; j++) acc += sAB[j * 36 + r] * sv[j];
            sQ[r] = acc;
        }
        __syncthreads();

        // ---- stage B'/C' (overlapped):
        //   warp0: Quu rows (12 thr, row-contiguous) -> syncwarp -> GJ [Quu|I|Qu] -> sQi, kv
        //   warps1-3: Qxx (21 tiles) + Qux (12 tiles) -> sH
        if (tid < 32) {
            if (tid < 12) {
                const ulonglong2 c2 = *(const ulonglong2*)(sCb + u_row * 36 + u_k0);
                ull aL = c2.x, aH = c2.y;
                #pragma unroll
                for (int j = 0; j < 24; j++) {
                    const ull ar = pack2(sAB[j * 36 + u_row]);
                    const ulonglong2 gg = *(const ulonglong2*)(sG + j * 36 + u_k0);
                    ffma2(aL, ar, gg.x); ffma2(aH, ar, gg.y);
                }
                const float2 lo = unpack2(aL), hi = unpack2(aH);
                float v[4] = { lo.x, lo.y, hi.x, hi.y };
                const int d = u_row - u_k0;
                if (d >= 0 && d < 4) v[d] += REGU;
                *(float4*)(sH + u_row * 36 + u_k0) = make_float4(v[0], v[1], v[2], v[3]);
            }
            __syncwarp();

            const int seg = tid >> 3, r = tid & 7;
            float m[9];
            if (seg == 0) {
                #pragma unroll
                for (int j = 0; j < 8; j++)
                    m[j] = (j <= r) ? sH[(24 + r) * 36 + 24 + j]
                                    : sH[(24 + j) * 36 + 24 + r];
                m[8] = sQ[24 + r];
            } else {
                #pragma unroll
                for (int j = 0; j < 8; j++) m[j] = (j == r) ? 1.0f : 0.0f;
                m[8] = 0.f;
            }
            #pragma unroll
            for (int cc = 0; cc < 8; cc++) {
                const float p   = __shfl_sync(0xffffffffu, m[cc], cc);
                const float inv = __fdividef(1.0f, p);
                const float f   = __shfl_sync(0xffffffffu, m[cc], r);
                const float fi  = f * inv;
                const int src = ((seg & 1) << 3) | cc;
                float pr[9];
                #pragma unroll
                for (int j = 0; j < 9; j++) pr[j] = __shfl_sync(0xffffffffu, m[j], src);
                const bool isPiv = (r == cc);
                #pragma unroll
                for (int j = 0; j < 9; j++)
                    m[j] = isPiv ? (m[j] * inv) : (m[j] - fi * pr[j]);
            }
            if (seg == 0) {
                skv[r] = -m[8];
                g_kv[(size_t)(b * T_HOR + t) * 8 + r] = -m[8];
            } else if (seg == 1) {
                #pragma unroll
                for (int j = 0; j < 8; j++) sQi[r * 9 + j] = m[j];
            }
        } else if (tid < 98) {
            const int r0 = q_r0, k0 = q_k0;
            const ulonglong2 c0 = *(const ulonglong2*)(sCb + r0 * 36 + k0);
            const ulonglong2 c1 = *(const ulonglong2*)(sCb + (r0 + 1) * 36 + k0);
            ull aL0 = c0.x, aH0 = c0.y, aL1 = c1.x, aH1 = c1.y;
            #pragma unroll
            for (int j = 0; j < 24; j++) {
                const float2 aa = *(const float2*)(sAB + j * 36 + r0);
                const ulonglong2 gg = *(const ulonglong2*)(sG + j * 36 + k0);
                const ull a0 = pack2(aa.x), a1 = pack2(aa.y);
                ffma2(aL0, a0, gg.x); ffma2(aH0, a0, gg.y);
                ffma2(aL1, a1, gg.x); ffma2(aH1, a1, gg.y);
            }
            *(ulonglong2*)(sH + r0 * 36 + k0)       = make_ulonglong2(aL0, aH0);
            *(ulonglong2*)(sH + (r0 + 1) * 36 + k0) = make_ulonglong2(aL1, aH1);
        }
        __syncthreads();

        // ---- stage D: K = -Qi*Qux (48 thr) ; vn (thr 96..119)
        if (tid < 48) {
            const int a = tid / 6, k4 = (tid % 6) * 4;
            float a0 = 0.f, a1 = 0.f, a2 = 0.f, a3 = 0.f;
            #pragma unroll
            for (int bq = 0; bq < 8; bq++) {
                const float qab = sQi[a * 9 + bq];
                const float4 qx = *(const float4*)(sH + (24 + bq) * 36 + k4);
                a0 -= qab * qx.x; a1 -= qab * qx.y; a2 -= qab * qx.z; a3 -= qab * qx.w;
            }
            const float4 kv4 = make_float4(a0, a1, a2, a3);
            *(float4*)(sK + a * 28 + k4) = kv4;
            *(float4*)(g_K + (size_t)(b * T_HOR + t) * 192 + a * 24 + k4) = kv4;
        } else if (tid >= 96 && tid < 120) {
            const int i = tid - 96;
            float acc = sQ[i];
            #pragma unroll
            for (int a = 0; a < 8; a++) acc += sH[(24 + a) * 36 + i] * skv[a];
            sv[i] = acc;
        }
        __syncthreads();

        // ---- stage E: V = H + Qux^T K on lower tri, mirrored (42 thr, f32x2)
        if (tid < 42) {
            const int i0 = 4 * e_ti, k0 = 4 * e_tk;
            const int rh = i0 + (tid & 1) * 2;
            ull sL0 = 0, sH0 = 0, sL1 = 0, sH1 = 0;
            #pragma unroll
            for (int a = 0; a < 8; a++) {
                const float2 hi = *(const float2*)(sH + (24 + a) * 36 + rh);
                const ulonglong2 kk = *(const ulonglong2*)(sK + a * 28 + k0);
                const ull h0 = pack2(hi.x), h1 = pack2(hi.y);
                ffma2(sL0, h0, kk.x); ffma2(sH0, h0, kk.y);
                ffma2(sL1, h1, kk.x); ffma2(sH1, h1, kk.y);
            }
            const float2 s0a = unpack2(sL0), s0b = unpack2(sH0);
            const float2 s1a = unpack2(sL1), s1b = unpack2(sH1);
            const float S0[4] = { s0a.x, s0a.y, s0b.x, s0b.y };
            const float S1[4] = { s1a.x, s1a.y, s1b.x, s1b.y };
            const float4 h40 = *(const float4*)(sH + rh * 36 + k0);
            const float4 h41 = *(const float4*)(sH + (rh + 1) * 36 + k0);
            float v0[4], v1[4];
            #pragma unroll
            for (int c = 0; c < 4; c++) {
                v0[c] = (&h40.x)[c] + S0[c];
                v1[c] = (&h41.x)[c] + S1[c];
            }
            *(float4*)(sV + rh * 28 + k0)       = make_float4(v0[0], v0[1], v0[2], v0[3]);
            *(float4*)(sV + (rh + 1) * 28 + k0) = make_float4(v1[0], v1[1], v1[2], v1[3]);
            if (e_ti != e_tk) {
                #pragma unroll
                for (int c = 0; c < 4; c++) {
                    sV[(k0 + c) * 28 + rh]     = v0[c];
                    sV[(k0 + c) * 28 + rh + 1] = v1[c];
                }
            }
        }
        if (t > 0) asm volatile("cp.async.wait_group 0;" ::: "memory");
        __syncthreads();
        buf ^= 1;
    }

    // ---------------- forward rollout (2 barriers/step, reg-direct K) ----------------
    float* ob = d_out + (size_t)b * 3224;
    if (tid < 24) {
        const float xi = d_x0[b * 24 + tid];
        sx[0][tid] = xi;
        ob[tid] = xi;
    }
    const int fa = tid >> 4, fl = tid & 15;
    float kr0 = 0.f, kr1 = 0.f;
    if (fl < 12) {
        kr0 = g_K[(size_t)b * T_HOR * 192 + fa * 24 + fl];
        kr1 = g_K[(size_t)b * T_HOR * 192 + fa * 24 + fl + 12];
    } else if (fl == 12) {
        kr0 = g_kv[(size_t)b * T_HOR * 8 + fa];
    }
    __syncthreads();

    int cur = 0;
    for (int t = 0; t < T_HOR; t++) {
        // u = K x + kv (16 thr per control; lane 12 injects kv)
        float p = (fl < 12) ? (kr0 * sx[cur][fl] + kr1 * sx[cur][fl + 12])
                            : ((fl == 12) ? kr0 : 0.f);
        p += __shfl_down_sync(0xffffffffu, p, 8, 16);
        p += __shfl_down_sync(0xffffffffu, p, 4, 16);
        p += __shfl_down_sync(0xffffffffu, p, 2, 16);
        p += __shfl_down_sync(0xffffffffu, p, 1, 16);
        if (fl == 0) {
            su[fa] = p;
            ob[2424 + t * 8 + fa] = p;
        }
        // prefetch next K/kv
        if (t < T_HOR - 1) {
            const size_t base = (size_t)(b * T_HOR + t + 1);
            if (fl < 12) {
                kr0 = g_K[base * 192 + fa * 24 + fl];
                kr1 = g_K[base * 192 + fa * 24 + fl + 12];
            } else if (fl == 12) {
                kr0 = g_kv[base * 8 + fa];
            }
        }
        __syncthreads();
        // x' = A x + B u
        if (tid < 24) {
            float acc = 0.f;
            #pragma unroll
            for (int j = 0; j < 24; j++) acc += sAB[tid * 36 + j] * sx[cur][j];
            #pragma unroll
            for (int a = 0; a < 8; a++) acc += sAB[tid * 36 + 24 + a] * su[a];
            sx[1 - cur][tid] = acc;
            ob[(t + 1) * 24 + tid] = acc;
        }
        __syncthreads();
        cur = 1 - cur;
    }
}

extern "C" void kernel_launch(void* const* d_in, const int* in_sizes, int n_in,
                              void* d_out, int out_size)
{
    const float* x0   = (const float*)d_in[0];
    const float* C    = (const float*)d_in[1];
    const float* c    = (const float*)d_in[2];
    const float* Cf   = (const float*)d_in[3];
    const float* cf   = (const float*)d_in[4];
    const float* xref = (const float*)d_in[5];
    const float* uref = (const float*)d_in[6];
    const float* A    = (const float*)d_in[7];
    const float* B    = (const float*)d_in[8];

    lqr_kernel<<<B_BATCH, 128>>>(x0, C, c, Cf, cf, xref, uref, A, B, (float*)d_out);
}

// round 10
// speedup vs baseline: 1.0752x; 1.0752x over previous
#include <cuda_runtime.h>

#define T_HOR 100
#define B_BATCH 512
#define REGU 1e-6f

typedef unsigned long long ull;

__device__ float g_K[B_BATCH * T_HOR * 8 * 24];
__device__ float g_kv[B_BATCH * T_HOR * 8];

__device__ __forceinline__ ull pack2(float s) {
    ull d; asm("mov.b64 %0, {%1, %1};" : "=l"(d) : "f"(s)); return d;
}
__device__ __forceinline__ void ffma2(ull& d, ull a, ull b) {
    asm("fma.rn.f32x2 %0, %1, %2, %0;" : "+l"(d) : "l"(a), "l"(b));
}
__device__ __forceinline__ float2 unpack2(ull v) {
    float2 r; asm("mov.b64 {%0, %1}, %2;" : "=f"(r.x), "=f"(r.y) : "l"(v)); return r;
}
__device__ __forceinline__ void cp16(unsigned sa, const void* g) {
    asm volatile("cp.async.cg.shared.global [%0], [%1], 16;" :: "r"(sa), "l"(g));
}
__device__ __forceinline__ void cp4(unsigned sa, const void* g) {
    asm volatile("cp.async.ca.shared.global [%0], [%1], 4;" :: "r"(sa), "l"(g));
}

extern "C" __global__ void __launch_bounds__(128, 4)
lqr_kernel(const float* __restrict__ d_x0,
           const float* __restrict__ d_C,
           const float* __restrict__ d_c,
           const float* __restrict__ d_Cf,
           const float* __restrict__ d_cf,
           const float* __restrict__ d_xref,
           const float* __restrict__ d_uref,
           const float* __restrict__ d_A,
           const float* __restrict__ d_B,
           float* __restrict__ d_out)
{
    __shared__ __align__(16) float sAB[24 * 36];
    __shared__ __align__(16) float sV[24 * 28];
    __shared__ __align__(16) float sC[2][32 * 36];
    __shared__ __align__(16) float sSc[2][64];     // [0..31]=c, [32..55]=xref, [56..63]=uref
    __shared__ __align__(16) float sG[24 * 36];
    __shared__ __align__(16) float sH[32 * 36];
    __shared__ __align__(16) float sK[8 * 28];
    __shared__ __align__(16) float sQ[32], sv[32];
    __shared__ float skv[8], su[8];
    __shared__ float sx[2][24];

    const int tid = threadIdx.x;
    const int b = blockIdx.x;

    // stage E map: tid>>1 over 21 lower tiles (6x6)
    int e_ti = 0, e_tk = 0;
    {
        const int tt = tid >> 1;
        int s = 0;
        #pragma unroll
        for (int i = 0; i < 6; i++) {
            if (tt >= s && tt < s + i + 1) { e_ti = i; e_tk = tt - s; }
            s += i + 1;
        }
    }
    // stage C Qxx map: (tid-32)>>1 over 21 lower tiles, valid tid 32..73
    int c_bi = 0, c_bk = 0;
    {
        const int tt = (tid - 32) >> 1;
        int s = 0;
        #pragma unroll
        for (int i = 0; i < 6; i++) {
            if (tt >= s && tt < s + i + 1) { c_bi = i; c_bk = tt - s; }
            s += i + 1;
        }
    }
    // stage B1 map (tid<60): 15 tiles (Qux 12 + Quu 3), 1 row x 4 cols
    int b1_r = 24, b1_k0 = 24;
    {
        const int tile = tid >> 2, rowin = tid & 3;
        if (tile < 6)        { b1_r = 24 + rowin; b1_k0 = tile * 4; }
        else if (tile < 12)  { b1_r = 28 + rowin; b1_k0 = (tile - 6) * 4; }
        else if (tile == 12) { b1_r = 24 + rowin; b1_k0 = 24; }
        else if (tile == 13) { b1_r = 28 + rowin; b1_k0 = 24; }
        else                 { b1_r = 28 + rowin; b1_k0 = 28; }
    }

    // ---------------- preamble ----------------
    for (int e = tid; e < 24 * 32; e += 128) {
        int j = e >> 5, cc = e & 31;
        sAB[j * 36 + cc] = (cc < 24) ? d_A[j * 24 + cc] : d_B[j * 8 + (cc - 24)];
    }
    for (int e = tid; e < 576; e += 128) {
        int i = e / 24, j = e - i * 24;
        sV[i * 28 + j] = d_Cf[(size_t)b * 1024 + i * 32 + j];
    }
    if (tid < 24) sQ[tid] = d_xref[((size_t)b * 101 + 100) * 24 + tid];
    {
        const float4* C4 = (const float4*)(d_C + ((size_t)b * T_HOR + 99) * 1024);
        #pragma unroll
        for (int ss = 0; ss < 2; ss++) {
            const int s = tid + ss * 128;
            *(float4*)(sC[0] + (s >> 3) * 36 + ((s & 7) << 2)) = C4[s];
        }
        if (tid < 32)
            sSc[0][tid] = d_c[((size_t)b * T_HOR + 99) * 32 + tid];
        else if (tid < 56)
            sSc[0][tid] = d_xref[((size_t)b * 101 + 99) * 24 + (tid - 32)];
        else if (tid < 64)
            sSc[0][tid] = d_uref[((size_t)b * T_HOR + 99) * 8 + (tid - 56)];
    }
    __syncthreads();
    if (tid < 24) {
        float acc = d_cf[b * 32 + tid];
        #pragma unroll
        for (int j = 0; j < 24; j++) acc -= sV[tid * 28 + j] * sQ[j];
        sv[tid] = acc;
    }
    __syncthreads();

    // ---------------- backward Riccati ----------------
    int buf = 0;
    for (int t = 99; t >= 0; --t) {
        const float* sCb  = sC[buf];
        const float* sScb = sSc[buf];

        if (t > 0) {
            const float4* src = (const float4*)(d_C + ((size_t)b * T_HOR + t - 1) * 1024);
            float* dst = sC[buf ^ 1];
            #pragma unroll
            for (int ss = 0; ss < 2; ss++) {
                const int s = tid + ss * 128;
                cp16((unsigned)__cvta_generic_to_shared(dst + (s >> 3) * 36 + ((s & 7) << 2)),
                     src + s);
            }
            if (tid < 64) {
                const float* g;
                if (tid < 32)      g = d_c    + ((size_t)b * T_HOR + t - 1) * 32 + tid;
                else if (tid < 56) g = d_xref + ((size_t)b * 101 + t - 1) * 24 + (tid - 32);
                else               g = d_uref + ((size_t)b * T_HOR + t - 1) * 8 + (tid - 56);
                cp4((unsigned)__cvta_generic_to_shared(&sSc[buf ^ 1][tid]), g);
            }
            asm volatile("cp.async.commit_group;");
        }

        // ---- stage A: G = V*[A|B] (96 thr, 2x4, f32x2) ; Q = [Qx|Qu] (32 thr)
        if (tid < 96) {
            const int i0 = (tid >> 3) * 2, c4 = (tid & 7) << 2;
            ull aL0 = 0, aH0 = 0, aL1 = 0, aH1 = 0;
            #pragma unroll
            for (int j = 0; j < 24; j++) {
                const float2 vv = *(const float2*)(sV + j * 28 + i0);
                const ulonglong2 ab = *(const ulonglong2*)(sAB + j * 36 + c4);
                const ull v0 = pack2(vv.x), v1 = pack2(vv.y);
                ffma2(aL0, v0, ab.x); ffma2(aH0, v0, ab.y);
                ffma2(aL1, v1, ab.x); ffma2(aH1, v1, ab.y);
            }
            *(ulonglong2*)(sG + i0 * 36 + c4)       = make_ulonglong2(aL0, aH0);
            *(ulonglong2*)(sG + (i0 + 1) * 36 + c4) = make_ulonglong2(aL1, aH1);
        } else {
            const int r = tid - 96;
            float acc = sScb[r];
            #pragma unroll
            for (int j4 = 0; j4 < 8; j4++) {
                const float4 cr = *(const float4*)(sCb + r * 36 + j4 * 4);
                const float4 zz = *(const float4*)(sScb + 32 + j4 * 4);
                acc -= cr.x * zz.x + cr.y * zz.y + cr.z * zz.z + cr.w * zz.w;
            }
            #pragma unroll
            for (int j = 0; j < 24; j++) acc += sAB[j * 36 + r] * sv[j];
            sQ[r] = acc;
        }
        __syncthreads();

        // ---- stage B1: Quu + Qux only (15 tiles, 60 thr, 1x4, f32x2)
        if (tid < 60) {
            const int r = b1_r, k0 = b1_k0;
            const ulonglong2 c2 = *(const ulonglong2*)(sCb + r * 36 + k0);
            ull aL = c2.x, aH = c2.y;
            #pragma unroll
            for (int j = 0; j < 24; j++) {
                const ull ar = pack2(sAB[j * 36 + r]);
                const ulonglong2 gg = *(const ulonglong2*)(sG + j * 36 + k0);
                ffma2(aL, ar, gg.x); ffma2(aH, ar, gg.y);
            }
            const float2 lo = unpack2(aL), hi = unpack2(aH);
            float v[4] = { lo.x, lo.y, hi.x, hi.y };
            const int d = r - k0;
            if (d >= 0 && d < 4) v[d] += REGU;
            *(float4*)(sH + r * 36 + k0) = make_float4(v[0], v[1], v[2], v[3]);
        }
        __syncthreads();

        // ---- stage C: warp0 augmented GJ [Quu|Qux|Qu] -> K, kv
        //      threads 32..73: Qxx (21 lower tiles, 2x4, f32x2)
        if (tid < 32) {
            const int seg = tid >> 3, r = tid & 7;
            float m[9];
            if (seg == 0) {
                #pragma unroll
                for (int j = 0; j < 8; j++)
                    m[j] = (j <= r) ? sH[(24 + r) * 36 + 24 + j]
                                    : sH[(24 + j) * 36 + 24 + r];
                m[8] = sQ[24 + r];
            } else {
                const int cb = (seg - 1) * 8;
                #pragma unroll
                for (int j = 0; j < 8; j++)
                    m[j] = sH[(24 + r) * 36 + cb + j];
                m[8] = 0.f;
            }
            #pragma unroll
            for (int cc = 0; cc < 8; cc++) {
                const float p   = __shfl_sync(0xffffffffu, m[cc], cc);
                const float inv = __fdividef(1.0f, p);
                const float f   = __shfl_sync(0xffffffffu, m[cc], r);
                const float fi  = f * inv;
                const int src = (seg << 3) | cc;
                float pr[9];
                #pragma unroll
                for (int j = 0; j < 9; j++) pr[j] = __shfl_sync(0xffffffffu, m[j], src);
                const bool isPiv = (r == cc);
                #pragma unroll
                for (int j = 0; j < 9; j++)
                    m[j] = isPiv ? (m[j] * inv) : (m[j] - fi * pr[j]);
            }
            if (seg == 0) {
                skv[r] = -m[8];
                g_kv[(size_t)(b * T_HOR + t) * 8 + r] = -m[8];
            } else {
                const int cb = (seg - 1) * 8;
                const float4 k0v = make_float4(-m[0], -m[1], -m[2], -m[3]);
                const float4 k1v = make_float4(-m[4], -m[5], -m[6], -m[7]);
                *(float4*)(sK + r * 28 + cb)     = k0v;
                *(float4*)(sK + r * 28 + cb + 4) = k1v;
                float* gk = g_K + (size_t)(b * T_HOR + t) * 192 + r * 24 + cb;
                *(float4*)gk       = k0v;
                *(float4*)(gk + 4) = k1v;
            }
        } else if (tid < 74) {
            const int r0 = c_bi * 4 + ((tid - 32) & 1) * 2;
            const int k0 = c_bk * 4;
            const ulonglong2 c0 = *(const ulonglong2*)(sCb + r0 * 36 + k0);
            const ulonglong2 c1 = *(const ulonglong2*)(sCb + (r0 + 1) * 36 + k0);
            ull aL0 = c0.x, aH0 = c0.y, aL1 = c1.x, aH1 = c1.y;
            #pragma unroll
            for (int j = 0; j < 24; j++) {
                const float2 aa = *(const float2*)(sAB + j * 36 + r0);
                const ulonglong2 gg = *(const ulonglong2*)(sG + j * 36 + k0);
                const ull a0 = pack2(aa.x), a1 = pack2(aa.y);
                ffma2(aL0, a0, gg.x); ffma2(aH0, a0, gg.y);
                ffma2(aL1, a1, gg.x); ffma2(aH1, a1, gg.y);
            }
            *(ulonglong2*)(sH + r0 * 36 + k0)       = make_ulonglong2(aL0, aH0);
            *(ulonglong2*)(sH + (r0 + 1) * 36 + k0) = make_ulonglong2(aL1, aH1);
        }
        __syncthreads();

        // ---- stage E: V = H + Qux^T K on lower tri, mirrored (42 thr) ; vn (24 thr)
        if (tid < 42) {
            const int i0 = 4 * e_ti, k0 = 4 * e_tk;
            const int rh = i0 + (tid & 1) * 2;
            ull sL0 = 0, sH0 = 0, sL1 = 0, sH1 = 0;
            #pragma unroll
            for (int a = 0; a < 8; a++) {
                const float2 hi = *(const float2*)(sH + (24 + a) * 36 + rh);
                const ulonglong2 kk = *(const ulonglong2*)(sK + a * 28 + k0);
                const ull h0 = pack2(hi.x), h1 = pack2(hi.y);
                ffma2(sL0, h0, kk.x); ffma2(sH0, h0, kk.y);
                ffma2(sL1, h1, kk.x); ffma2(sH1, h1, kk.y);
            }
            const float2 s0a = unpack2(sL0), s0b = unpack2(sH0);
            const float2 s1a = unpack2(sL1), s1b = unpack2(sH1);
            const float S0[4] = { s0a.x, s0a.y, s0b.x, s0b.y };
            const float S1[4] = { s1a.x, s1a.y, s1b.x, s1b.y };
            const float4 h40 = *(const float4*)(sH + rh * 36 + k0);
            const float4 h41 = *(const float4*)(sH + (rh + 1) * 36 + k0);
            float v0[4], v1[4];
            #pragma unroll
            for (int c = 0; c < 4; c++) {
                v0[c] = (&h40.x)[c] + S0[c];
                v1[c] = (&h41.x)[c] + S1[c];
            }
            *(float4*)(sV + rh * 28 + k0)       = make_float4(v0[0], v0[1], v0[2], v0[3]);
            *(float4*)(sV + (rh + 1) * 28 + k0) = make_float4(v1[0], v1[1], v1[2], v1[3]);
            if (e_ti != e_tk) {
                #pragma unroll
                for (int c = 0; c < 4; c++) {
                    sV[(k0 + c) * 28 + rh]     = v0[c];
                    sV[(k0 + c) * 28 + rh + 1] = v1[c];
                }
            }
        } else if (tid >= 96 && tid < 120) {
            const int i = tid - 96;
            float acc = sQ[i];
            #pragma unroll
            for (int a = 0; a < 8; a++) acc += sH[(24 + a) * 36 + i] * skv[a];
            sv[i] = acc;
        }
        if (t > 0) asm volatile("cp.async.wait_group 0;" ::: "memory");
        __syncthreads();
        buf ^= 1;
    }

    // ---------------- forward rollout (2 barriers/step, reg-direct K) ----------------
    float* ob = d_out + (size_t)b * 3224;
    if (tid < 24) {
        const float xi = d_x0[b * 24 + tid];
        sx[0][tid] = xi;
        ob[tid] = xi;
    }
    const int fa = tid >> 4, fl = tid & 15;
    float kr0 = 0.f, kr1 = 0.f;
    if (fl < 12) {
        kr0 = g_K[(size_t)b * T_HOR * 192 + fa * 24 + fl];
        kr1 = g_K[(size_t)b * T_HOR * 192 + fa * 24 + fl + 12];
    } else if (fl == 12) {
        kr0 = g_kv[(size_t)b * T_HOR * 8 + fa];
    }
    __syncthreads();

    int cur = 0;
    for (int t = 0; t < T_HOR; t++) {
        float p = (fl < 12) ? (kr0 * sx[cur][fl] + kr1 * sx[cur][fl + 12])
                            : ((fl == 12) ? kr0 : 0.f);
        p += __shfl_down_sync(0xffffffffu, p, 8, 16);
        p += __shfl_down_sync(0xffffffffu, p, 4, 16);
        p += __shfl_down_sync(0xffffffffu, p, 2, 16);
        p += __shfl_down_sync(0xffffffffu, p, 1, 16);
        if (fl == 0) {
            su[fa] = p;
            ob[2424 + t * 8 + fa] = p;
        }
        if (t < T_HOR - 1) {
            const size_t base = (size_t)(b * T_HOR + t + 1);
            if (fl < 12) {
                kr0 = g_K[base * 192 + fa * 24 + fl];
                kr1 = g_K[base * 192 + fa * 24 + fl + 12];
            } else if (fl == 12) {
                kr0 = g_kv[base * 8 + fa];
            }
        }
        __syncthreads();
        if (tid < 24) {
            float acc = 0.f;
            #pragma unroll
            for (int j = 0; j < 24; j++) acc += sAB[tid * 36 + j] * sx[cur][j];
            #pragma unroll
            for (int a = 0; a < 8; a++) acc += sAB[tid * 36 + 24 + a] * su[a];
            sx[1 - cur][tid] = acc;
            ob[(t + 1) * 24 + tid] = acc;
        }
        __syncthreads();
        cur = 1 - cur;
    }
}

extern "C" void kernel_launch(void* const* d_in, const int* in_sizes, int n_in,
                              void* d_out, int out_size)
{
    const float* x0   = (const float*)d_in[0];
    const float* C    = (const float*)d_in[1];
    const float* c    = (const float*)d_in[2];
    const float* Cf   = (const float*)d_in[3];
    const float* cf   = (const float*)d_in[4];
    const float* xref = (const float*)d_in[5];
    const float* uref = (const float*)d_in[6];
    const float* A    = (const float*)d_in[7];
    const float* B    = (const float*)d_in[8];

    lqr_kernel<<<B_BATCH, 128>>>(x0, C, c, Cf, cf, xref, uref, A, B, (float*)d_out);
}

// round 11
// speedup vs baseline: 1.0765x; 1.0012x over previous
#include <cuda_runtime.h>

#define T_HOR 100
#define B_BATCH 512
#define REGU 1e-6f

typedef unsigned long long ull;

__device__ float g_K[B_BATCH * T_HOR * 8 * 24];
__device__ float g_kv[B_BATCH * T_HOR * 8];

__device__ __forceinline__ ull pack2(float s) {
    ull d; asm("mov.b64 %0, {%1, %1};" : "=l"(d) : "f"(s)); return d;
}
__device__ __forceinline__ void ffma2(ull& d, ull a, ull b) {
    asm("fma.rn.f32x2 %0, %1, %2, %0;" : "+l"(d) : "l"(a), "l"(b));
}
__device__ __forceinline__ float2 unpack2(ull v) {
    float2 r; asm("mov.b64 {%0, %1}, %2;" : "=f"(r.x), "=f"(r.y) : "l"(v)); return r;
}
__device__ __forceinline__ void cp16(unsigned sa, const void* g) {
    asm volatile("cp.async.cg.shared.global [%0], [%1], 16;" :: "r"(sa), "l"(g));
}
__device__ __forceinline__ void cp4(unsigned sa, const void* g) {
    asm volatile("cp.async.ca.shared.global [%0], [%1], 4;" :: "r"(sa), "l"(g));
}

extern "C" __global__ void __launch_bounds__(128, 4)
lqr_kernel(const float* __restrict__ d_x0,
           const float* __restrict__ d_C,
           const float* __restrict__ d_c,
           const float* __restrict__ d_Cf,
           const float* __restrict__ d_cf,
           const float* __restrict__ d_xref,
           const float* __restrict__ d_uref,
           const float* __restrict__ d_A,
           const float* __restrict__ d_B,
           float* __restrict__ d_out)
{
    __shared__ __align__(16) float sAB[24 * 36];
    __shared__ __align__(16) float sV[24 * 28];
    __shared__ __align__(16) float sC[2][32 * 36];
    __shared__ __align__(16) float sSc[2][64];     // [0..31]=c, [32..55]=xref, [56..63]=uref
    __shared__ __align__(16) float sG[24 * 36];
    __shared__ __align__(16) float sH[32 * 36];
    __shared__ __align__(16) float sK[8 * 28];
    __shared__ __align__(16) float sQ[32], sv[32];
    __shared__ float skv[8];
    __shared__ float sx[24];

    const int tid = threadIdx.x;
    const int b = blockIdx.x;

    // stage E map: tid>>1 over 21 lower tiles (6x6)
    int e_ti = 0, e_tk = 0;
    {
        const int tt = tid >> 1;
        int s = 0;
        #pragma unroll
        for (int i = 0; i < 6; i++) {
            if (tt >= s && tt < s + i + 1) { e_ti = i; e_tk = tt - s; }
            s += i + 1;
        }
    }
    // stage C Qxx map: (tid-32)>>1 over 21 lower tiles, valid tid 32..73
    int c_bi = 0, c_bk = 0;
    {
        const int tt = (tid - 32) >> 1;
        int s = 0;
        #pragma unroll
        for (int i = 0; i < 6; i++) {
            if (tt >= s && tt < s + i + 1) { c_bi = i; c_bk = tt - s; }
            s += i + 1;
        }
    }
    // stage B1 map (tid<60): 15 tiles (Qux 12 + Quu 3), 1 row x 4 cols
    int b1_r = 24, b1_k0 = 24;
    {
        const int tile = tid >> 2, rowin = tid & 3;
        if (tile < 6)        { b1_r = 24 + rowin; b1_k0 = tile * 4; }
        else if (tile < 12)  { b1_r = 28 + rowin; b1_k0 = (tile - 6) * 4; }
        else if (tile == 12) { b1_r = 24 + rowin; b1_k0 = 24; }
        else if (tile == 13) { b1_r = 28 + rowin; b1_k0 = 24; }
        else                 { b1_r = 28 + rowin; b1_k0 = 28; }
    }

    // ---------------- preamble ----------------
    for (int e = tid; e < 24 * 32; e += 128) {
        int j = e >> 5, cc = e & 31;
        sAB[j * 36 + cc] = (cc < 24) ? d_A[j * 24 + cc] : d_B[j * 8 + (cc - 24)];
    }
    for (int e = tid; e < 576; e += 128) {
        int i = e / 24, j = e - i * 24;
        sV[i * 28 + j] = d_Cf[(size_t)b * 1024 + i * 32 + j];
    }
    if (tid < 24) sQ[tid] = d_xref[((size_t)b * 101 + 100) * 24 + tid];
    {
        const float4* C4 = (const float4*)(d_C + ((size_t)b * T_HOR + 99) * 1024);
        #pragma unroll
        for (int ss = 0; ss < 2; ss++) {
            const int s = tid + ss * 128;
            *(float4*)(sC[0] + (s >> 3) * 36 + ((s & 7) << 2)) = C4[s];
        }
        if (tid < 32)
            sSc[0][tid] = d_c[((size_t)b * T_HOR + 99) * 32 + tid];
        else if (tid < 56)
            sSc[0][tid] = d_xref[((size_t)b * 101 + 99) * 24 + (tid - 32)];
        else if (tid < 64)
            sSc[0][tid] = d_uref[((size_t)b * T_HOR + 99) * 8 + (tid - 56)];
    }
    __syncthreads();
    if (tid < 24) {
        float acc = d_cf[b * 32 + tid];
        #pragma unroll
        for (int j = 0; j < 24; j++) acc -= sV[tid * 28 + j] * sQ[j];
        sv[tid] = acc;
    }
    __syncthreads();

    // ---------------- backward Riccati ----------------
    int buf = 0;
    for (int t = 99; t >= 0; --t) {
        const float* sCb  = sC[buf];
        const float* sScb = sSc[buf];

        if (t > 0) {
            const float4* src = (const float4*)(d_C + ((size_t)b * T_HOR + t - 1) * 1024);
            float* dst = sC[buf ^ 1];
            #pragma unroll
            for (int ss = 0; ss < 2; ss++) {
                const int s = tid + ss * 128;
                cp16((unsigned)__cvta_generic_to_shared(dst + (s >> 3) * 36 + ((s & 7) << 2)),
                     src + s);
            }
            if (tid < 64) {
                const float* g;
                if (tid < 32)      g = d_c    + ((size_t)b * T_HOR + t - 1) * 32 + tid;
                else if (tid < 56) g = d_xref + ((size_t)b * 101 + t - 1) * 24 + (tid - 32);
                else               g = d_uref + ((size_t)b * T_HOR + t - 1) * 8 + (tid - 56);
                cp4((unsigned)__cvta_generic_to_shared(&sSc[buf ^ 1][tid]), g);
            }
            asm volatile("cp.async.commit_group;");
        }

        // ---- stage A: G = V*[A|B] (96 thr, 2x4, f32x2) ; Q = [Qx|Qu] (32 thr)
        if (tid < 96) {
            const int i0 = (tid >> 3) * 2, c4 = (tid & 7) << 2;
            ull aL0 = 0, aH0 = 0, aL1 = 0, aH1 = 0;
            #pragma unroll
            for (int j = 0; j < 24; j++) {
                const float2 vv = *(const float2*)(sV + j * 28 + i0);
                const ulonglong2 ab = *(const ulonglong2*)(sAB + j * 36 + c4);
                const ull v0 = pack2(vv.x), v1 = pack2(vv.y);
                ffma2(aL0, v0, ab.x); ffma2(aH0, v0, ab.y);
                ffma2(aL1, v1, ab.x); ffma2(aH1, v1, ab.y);
            }
            *(ulonglong2*)(sG + i0 * 36 + c4)       = make_ulonglong2(aL0, aH0);
            *(ulonglong2*)(sG + (i0 + 1) * 36 + c4) = make_ulonglong2(aL1, aH1);
        } else {
            const int r = tid - 96;
            float acc = sScb[r];
            #pragma unroll
            for (int j4 = 0; j4 < 8; j4++) {
                const float4 cr = *(const float4*)(sCb + r * 36 + j4 * 4);
                const float4 zz = *(const float4*)(sScb + 32 + j4 * 4);
                acc -= cr.x * zz.x + cr.y * zz.y + cr.z * zz.z + cr.w * zz.w;
            }
            #pragma unroll
            for (int j = 0; j < 24; j++) acc += sAB[j * 36 + r] * sv[j];
            sQ[r] = acc;
        }
        __syncthreads();

        // ---- stage B1: Quu + Qux only (15 tiles, 60 thr, 1x4, f32x2)
        if (tid < 60) {
            const int r = b1_r, k0 = b1_k0;
            const ulonglong2 c2 = *(const ulonglong2*)(sCb + r * 36 + k0);
            ull aL = c2.x, aH = c2.y;
            #pragma unroll
            for (int j = 0; j < 24; j++) {
                const ull ar = pack2(sAB[j * 36 + r]);
                const ulonglong2 gg = *(const ulonglong2*)(sG + j * 36 + k0);
                ffma2(aL, ar, gg.x); ffma2(aH, ar, gg.y);
            }
            const float2 lo = unpack2(aL), hi = unpack2(aH);
            float v[4] = { lo.x, lo.y, hi.x, hi.y };
            const int d = r - k0;
            if (d >= 0 && d < 4) v[d] += REGU;
            *(float4*)(sH + r * 36 + k0) = make_float4(v[0], v[1], v[2], v[3]);
        }
        __syncthreads();

        // ---- stage C: warp0 augmented GJ [Quu|Qux|Qu] -> K, kv (smem only; gmem spill in E)
        //      threads 32..73: Qxx (21 lower tiles, 2x4, f32x2)
        if (tid < 32) {
            const int seg = tid >> 3, r = tid & 7;
            float m[9];
            if (seg == 0) {
                #pragma unroll
                for (int j = 0; j < 8; j++)
                    m[j] = (j <= r) ? sH[(24 + r) * 36 + 24 + j]
                                    : sH[(24 + j) * 36 + 24 + r];
                m[8] = sQ[24 + r];
            } else {
                const int cb = (seg - 1) * 8;
                #pragma unroll
                for (int j = 0; j < 8; j++)
                    m[j] = sH[(24 + r) * 36 + cb + j];
                m[8] = 0.f;
            }
            #pragma unroll
            for (int cc = 0; cc < 8; cc++) {
                const float p   = __shfl_sync(0xffffffffu, m[cc], cc);
                const float inv = __fdividef(1.0f, p);
                const float f   = __shfl_sync(0xffffffffu, m[cc], r);
                const float fi  = f * inv;
                const int src = (seg << 3) | cc;
                float pr[9];
                #pragma unroll
                for (int j = 0; j < 9; j++) pr[j] = __shfl_sync(0xffffffffu, m[j], src);
                const bool isPiv = (r == cc);
                #pragma unroll
                for (int j = 0; j < 9; j++)
                    m[j] = isPiv ? (m[j] * inv) : (m[j] - fi * pr[j]);
            }
            if (seg == 0) {
                skv[r] = -m[8];
            } else {
                const int cb = (seg - 1) * 8;
                *(float4*)(sK + r * 28 + cb)     = make_float4(-m[0], -m[1], -m[2], -m[3]);
                *(float4*)(sK + r * 28 + cb + 4) = make_float4(-m[4], -m[5], -m[6], -m[7]);
            }
        } else if (tid < 74) {
            const int r0 = c_bi * 4 + ((tid - 32) & 1) * 2;
            const int k0 = c_bk * 4;
            const ulonglong2 c0 = *(const ulonglong2*)(sCb + r0 * 36 + k0);
            const ulonglong2 c1 = *(const ulonglong2*)(sCb + (r0 + 1) * 36 + k0);
            ull aL0 = c0.x, aH0 = c0.y, aL1 = c1.x, aH1 = c1.y;
            #pragma unroll
            for (int j = 0; j < 24; j++) {
                const float2 aa = *(const float2*)(sAB + j * 36 + r0);
                const ulonglong2 gg = *(const ulonglong2*)(sG + j * 36 + k0);
                const ull a0 = pack2(aa.x), a1 = pack2(aa.y);
                ffma2(aL0, a0, gg.x); ffma2(aH0, a0, gg.y);
                ffma2(aL1, a1, gg.x); ffma2(aH1, a1, gg.y);
            }
            *(ulonglong2*)(sH + r0 * 36 + k0)       = make_ulonglong2(aL0, aH0);
            *(ulonglong2*)(sH + (r0 + 1) * 36 + k0) = make_ulonglong2(aL1, aH1);
        }
        __syncthreads();

        // ---- stage E: V tiles (0..41) ; g_K spill (74..89) ; g_kv spill (90..97) ; vn (100..123)
        if (tid < 42) {
            const int i0 = 4 * e_ti, k0 = 4 * e_tk;
            const int rh = i0 + (tid & 1) * 2;
            ull sL0 = 0, sH0 = 0, sL1 = 0, sH1 = 0;
            #pragma unroll
            for (int a = 0; a < 8; a++) {
                const float2 hi = *(const float2*)(sH + (24 + a) * 36 + rh);
                const ulonglong2 kk = *(const ulonglong2*)(sK + a * 28 + k0);
                const ull h0 = pack2(hi.x), h1 = pack2(hi.y);
                ffma2(sL0, h0, kk.x); ffma2(sH0, h0, kk.y);
                ffma2(sL1, h1, kk.x); ffma2(sH1, h1, kk.y);
            }
            const float2 s0a = unpack2(sL0), s0b = unpack2(sH0);
            const float2 s1a = unpack2(sL1), s1b = unpack2(sH1);
            const float S0[4] = { s0a.x, s0a.y, s0b.x, s0b.y };
            const float S1[4] = { s1a.x, s1a.y, s1b.x, s1b.y };
            const float4 h40 = *(const float4*)(sH + rh * 36 + k0);
            const float4 h41 = *(const float4*)(sH + (rh + 1) * 36 + k0);
            float v0[4], v1[4];
            #pragma unroll
            for (int c = 0; c < 4; c++) {
                v0[c] = (&h40.x)[c] + S0[c];
                v1[c] = (&h41.x)[c] + S1[c];
            }
            *(float4*)(sV + rh * 28 + k0)       = make_float4(v0[0], v0[1], v0[2], v0[3]);
            *(float4*)(sV + (rh + 1) * 28 + k0) = make_float4(v1[0], v1[1], v1[2], v1[3]);
            if (e_ti != e_tk) {
                #pragma unroll
                for (int c = 0; c < 4; c++) {
                    sV[(k0 + c) * 28 + rh]     = v0[c];
                    sV[(k0 + c) * 28 + rh + 1] = v1[c];
                }
            }
        } else if (tid >= 74 && tid < 90) {
            const int i = tid - 74;            // 16 threads: row = i>>1, half = i&1
            const int row = i >> 1, cb = (i & 1) * 12;
            const float4 a0 = *(const float4*)(sK + row * 28 + cb);
            const float4 a1 = *(const float4*)(sK + row * 28 + cb + 4);
            const float4 a2 = *(const float4*)(sK + row * 28 + cb + 8);
            float* gk = g_K + (size_t)(b * T_HOR + t) * 192 + row * 24 + cb;
            *(float4*)(gk)     = a0;
            *(float4*)(gk + 4) = a1;
            *(float4*)(gk + 8) = a2;
        } else if (tid >= 90 && tid < 98) {
            g_kv[(size_t)(b * T_HOR + t) * 8 + (tid - 90)] = skv[tid - 90];
        } else if (tid >= 100 && tid < 124) {
            const int i = tid - 100;
            float acc = sQ[i];
            #pragma unroll
            for (int a = 0; a < 8; a++) acc += sH[(24 + a) * 36 + i] * skv[a];
            sv[i] = acc;
        }
        if (t > 0) asm volatile("cp.async.wait_group 0;" ::: "memory");
        __syncthreads();
        buf ^= 1;
    }

    // ---------------- forward rollout: warp 0 only, no __syncthreads ----------------
    if (tid >= 32) return;
    const int lane = tid;
    float* ob = d_out + (size_t)b * 3224;

    // bank-conflict-free [A|B] copy into sG space: row i (0..23), stride 33
    float* sAB2 = sG;
    for (int e = lane; e < 768; e += 32) {
        const int i = e >> 5, c = e & 31;
        sAB2[i * 33 + c] = sAB[i * 36 + c];
    }
    if (lane < 24) {
        const float xi = d_x0[b * 24 + lane];
        sx[lane] = xi;
        ob[lane] = xi;
    }
    float kc[24], kn[24], kvc = 0.f, kvn = 0.f;
    if (lane < 8) {
        const float* gk = g_K + (size_t)b * T_HOR * 192 + lane * 24;
        #pragma unroll
        for (int q = 0; q < 6; q++) {
            const float4 v = *(const float4*)(gk + q * 4);
            kc[q * 4 + 0] = v.x; kc[q * 4 + 1] = v.y;
            kc[q * 4 + 2] = v.z; kc[q * 4 + 3] = v.w;
        }
        kvc = g_kv[(size_t)b * T_HOR * 8 + lane];
    }
    __syncwarp();

    for (int t = 0; t < T_HOR; t++) {
        // prefetch K(t+1)
        if (lane < 8 && t + 1 < T_HOR) {
            const float* gk = g_K + (size_t)(b * T_HOR + t + 1) * 192 + lane * 24;
            #pragma unroll
            for (int q = 0; q < 6; q++) {
                const float4 v = *(const float4*)(gk + q * 4);
                kn[q * 4 + 0] = v.x; kn[q * 4 + 1] = v.y;
                kn[q * 4 + 2] = v.z; kn[q * 4 + 3] = v.w;
            }
            kvn = g_kv[(size_t)(b * T_HOR + t + 1) * 8 + lane];
        }
        // u = K x + kv  (lanes 0..7)
        float u = 0.f;
        if (lane < 8) {
            u = kvc;
            #pragma unroll
            for (int j = 0; j < 24; j++) u += kc[j] * sx[j];
            ob[2424 + t * 8 + lane] = u;
        }
        // broadcast u, compute x' = A x + B u (lanes 0..23)
        float acc = 0.f;
        {
            float ua[8];
            #pragma unroll
            for (int a = 0; a < 8; a++) ua[a] = __shfl_sync(0xffffffffu, u, a);
            if (lane < 24) {
                #pragma unroll
                for (int j = 0; j < 24; j++) acc += sAB2[lane * 33 + j] * sx[j];
                #pragma unroll
                for (int a = 0; a < 8; a++) acc += sAB2[lane * 33 + 24 + a] * ua[a];
            }
        }
        __syncwarp();
        if (lane < 24) {
            sx[lane] = acc;
            ob[(t + 1) * 24 + lane] = acc;
        }
        if (lane < 8) {
            #pragma unroll
            for (int q = 0; q < 24; q++) kc[q] = kn[q];
            kvc = kvn;
        }
        __syncwarp();
    }
}

extern "C" void kernel_launch(void* const* d_in, const int* in_sizes, int n_in,
                              void* d_out, int out_size)
{
    const float* x0   = (const float*)d_in[0];
    const float* C    = (const float*)d_in[1];
    const float* c    = (const float*)d_in[2];
    const float* Cf   = (const float*)d_in[3];
    const float* cf   = (const float*)d_in[4];
    const float* xref = (const float*)d_in[5];
    const float* uref = (const float*)d_in[6];
    const float* A    = (const float*)d_in[7];
    const float* B    = (const float*)d_in[8];

    lqr_kernel<<<B_BATCH, 128>>>(x0, C, c, Cf, cf, xref, uref, A, B, (float*)d_out);
}